// round 13
// baseline (speedup 1.0000x reference)
#include <cuda_runtime.h>
#include <cuda_bf16.h>

// Problem constants (fixed by setup_inputs):
//   encoder_output: (B=32, L_ENC=512, E=256) float32
//   durations:      (B=32, L_ENC=512) int32, values in [0, 8)
//   output:         (B=32, L_DEC=2048, E=256) float32
//
// out[b, d, :] = enc[b, l, :] where cs[l-1] <= d < cs[l]; 0 for d >= cs[511].

#define B_SZ    32
#define L_ENC   512
#define L_DEC   2048
#define E_DIM   256
#define E_VEC   (E_DIM / 4)            // 64 float4 per row
#define ROWS_PER_BLOCK 128             // decoder rows per block (2 tiles)
#define BLOCKS_PER_BATCH (L_DEC / ROWS_PER_BLOCK)   // 16
#define N_BLOCKS (B_SZ * BLOCKS_PER_BATCH)          // 512
#define ROWS_PER_GROUP (ROWS_PER_BLOCK / 8)         // 16 rows per 64-lane group

// ---------------------------------------------------------------------------
// Single fused kernel. Grid = 512 blocks, 512 threads.
// Per block (128 consecutive decoder rows of one batch):
//  1. load batch durations (2KB, L2-hot) + block-wide inclusive scan
//  2. scatter s_map[128]: decoder row -> enc row, -1 pad
//  3. gather: 8 groups of 64 lanes copy 16 consecutive 1KB rows each
// Halved CTA count (vs 64-row tiles) cuts cross-CTA L1tex-queue contention.
// ---------------------------------------------------------------------------
__global__ void __launch_bounds__(512)
lr_fused_kernel(const float4* __restrict__ enc,
                const int*    __restrict__ dur,
                float4* __restrict__ out)
{
    __shared__ int s_wsum[16];
    __shared__ int s_map[ROWS_PER_BLOCK];

    const int bid  = blockIdx.x;
    const int b    = bid >> 4;                // batch (16 blocks per batch)
    const int blk  = bid & 15;                // block within batch
    const int base = blk * ROWS_PER_BLOCK;    // decoder row base
    const int t    = threadIdx.x;
    const int wid  = t >> 5;
    const int lane = t & 31;

    // ---- 1. block-wide inclusive scan of this batch's 512 durations ----
    const int my_dur = dur[b * L_ENC + t];
    int v = my_dur;
    #pragma unroll
    for (int off = 1; off < 32; off <<= 1) {
        int u = __shfl_up_sync(0xffffffffu, v, off);
        if (lane >= off) v += u;
    }
    if (lane == 31) s_wsum[wid] = v;

    // init s_map while waiting (distinct smem; ordered by the same barrier)
    if (t < ROWS_PER_BLOCK) s_map[t] = -1;
    __syncthreads();

    if (wid == 0 && lane < 16) {
        int ws = s_wsum[lane];
        #pragma unroll
        for (int off = 1; off < 16; off <<= 1) {
            int u = __shfl_up_sync(0x0000ffffu, ws, off);
            if (lane >= off) ws += u;
        }
        s_wsum[lane] = ws - s_wsum[lane];     // exclusive prefix of warp sums
    }
    __syncthreads();

    const int incl = v + s_wsum[wid];         // inclusive cumsum at enc row t
    const int excl = incl - my_dur;

    // ---- 2. scatter: enc row t covers decoder rows [excl, incl) ----
    {
        int lo = excl > base ? excl : base;
        int hi = incl < base + ROWS_PER_BLOCK ? incl : base + ROWS_PER_BLOCK;
        for (int d = lo; d < hi; ++d)
            s_map[d - base] = t;              // each map slot written once
    }
    __syncthreads();

    // ---- 3. gather: group g copies rows base + g*16 .. +15 ----
    const int group = t >> 6;                 // 0..7
    const int glane = t & 63;                 // 0..63
    const int r0    = group * ROWS_PER_GROUP;

    const float4* enc_b = enc + ((long)b * L_ENC) * E_VEC;
    float4* out_rows = out + ((long)(b * L_DEC + base + r0)) * E_VEC;

    #pragma unroll
    for (int j = 0; j < ROWS_PER_GROUP; ++j) {
        const int src = s_map[r0 + j];        // broadcast LDS
        float4 vv;
        if (src >= 0)
            vv = __ldg(enc_b + (long)src * E_VEC + glane);
        else
            vv = make_float4(0.f, 0.f, 0.f, 0.f);
        out_rows[(long)j * E_VEC + glane] = vv;
    }
}

// ---------------------------------------------------------------------------
extern "C" void kernel_launch(void* const* d_in, const int* in_sizes, int n_in,
                              void* d_out, int out_size)
{
    const float* enc = (const float*)d_in[0];     // (B, L_ENC, E)
    const int*   dur = (const int*)d_in[1];       // (B, L_ENC) int32
    (void)in_sizes; (void)n_in; (void)out_size;

    lr_fused_kernel<<<N_BLOCKS, 512>>>((const float4*)enc, dur,
                                       (float4*)d_out);
}